// round 5
// baseline (speedup 1.0000x reference)
#include <cuda_runtime.h>
#include <math.h>

// Scratch: feat1, outs1, feat2, outs2, feat3, outs3, gates (all fp32)
__device__ float g_scratch[47448064];

__device__ __forceinline__ float sigf(float x) { return 1.f / (1.f + __expf(-x)); }
__device__ __forceinline__ float ftanh(float x) {
    float e = __expf(2.f * x);
    return 1.f - 2.f / (e + 1.f);
}

// ---------------------------------------------------------------------------
// Register-blocked GRU conv. RY=4: block(16,8), tile 32x32. RY=1: block(8,16),
// tile 16x16. Each thread: RY rows x 2 cols x 4 output channels.
// Channel chunks of 4 (one warp loads one channel plane).
// grid: (B * Cout/4, H/TILE, W/TILE)
// mode 0: gates (sigmoid -> gates buf). mode 1: cand conv on [x, r*h] + update.
// ---------------------------------------------------------------------------
template<int RY>
__global__ __launch_bounds__(128, 4)
void gru_conv3(const float* __restrict__ xt, const float* __restrict__ hprev,
               const float* __restrict__ Wt, const float* __restrict__ bias,
               const float* __restrict__ gatesIn, float* __restrict__ out,
               int Cx, int Ch, int Cout, int H, int W, int mode)
{
    constexpr int TILE = (RY == 4) ? 32 : 16;
    constexpr int LW   = TILE + 2;
    constexpr int SSTR = TILE + 4;

    const int cgrp = Cout >> 2;
    int b   = blockIdx.x / cgrp;
    int co0 = (blockIdx.x % cgrp) * 4;
    int oy0 = blockIdx.y * TILE;
    int ox0 = blockIdx.z * TILE;
    int tx = threadIdx.x, ty = threadIdx.y;
    int tid  = ty * blockDim.x + tx;
    int lane = tid & 31, warp = tid >> 5;

    __shared__ float tile[4][LW][SSTR];
    __shared__ __align__(16) float ws[4][4][12];

    int CinTot = Cx + Ch;
    int CinEff = hprev ? CinTot : Cx;   // h0 == 0 -> skip h channels at t=0
    int HW = H * W;

    float acc[4][RY][2];
#pragma unroll
    for (int co = 0; co < 4; co++)
#pragma unroll
        for (int r = 0; r < RY; r++) { acc[co][r][0] = 0.f; acc[co][r][1] = 0.f; }

    for (int ci0 = 0; ci0 < CinEff; ci0 += 4) {
        bool isH = (ci0 >= Cx);
        int cbase = (isH ? ci0 - Cx : ci0) + warp;
        const float* sp = (isH ? hprev : xt) + ((size_t)b * (isH ? Ch : Cx) + cbase) * HW;
        const float* rp = (isH && mode) ? gatesIn + ((size_t)b * 2 * Ch + cbase) * HW
                                        : nullptr;

        __syncthreads();
        // loader: warp w loads channel plane w of this chunk (LW x LW, zero halo)
        if (rp) {
#pragma unroll 2
            for (int r = 0; r < LW; r++) {
                int gy = oy0 - 1 + r;
                bool oky = (unsigned)gy < (unsigned)H;
                const float* rowp = sp + gy * W;
                const float* rrp  = rp + gy * W;
#pragma unroll
                for (int col = lane; col < LW; col += 32) {
                    int gx = ox0 - 1 + col;
                    float v = 0.f;
                    if (oky && (unsigned)gx < (unsigned)W) v = rowp[gx] * rrp[gx];
                    tile[warp][r][col] = v;
                }
            }
        } else {
#pragma unroll 2
            for (int r = 0; r < LW; r++) {
                int gy = oy0 - 1 + r;
                bool oky = (unsigned)gy < (unsigned)H;
                const float* rowp = sp + gy * W;
#pragma unroll
                for (int col = lane; col < LW; col += 32) {
                    int gx = ox0 - 1 + col;
                    float v = 0.f;
                    if (oky && (unsigned)gx < (unsigned)W) v = rowp[gx];
                    tile[warp][r][col] = v;
                }
            }
        }
        // weights for this chunk: 4c x 4co x 9 = 144 elements, 128 threads
        for (int i = tid; i < 144; i += 128) {
            int c = i / 36, rem = i % 36;
            int co = rem / 9, k = rem % 9;
            ws[c][co][k] = Wt[((size_t)(co0 + co) * CinTot + ci0 + c) * 9 + k];
        }
        __syncthreads();

#pragma unroll
        for (int c = 0; c < 4; c++) {
            float p[RY + 2][4];
#pragma unroll
            for (int rr = 0; rr < RY + 2; rr++) {
                float2 a = *(const float2*)&tile[c][ty * RY + rr][tx * 2];
                float2 bq = *(const float2*)&tile[c][ty * RY + rr][tx * 2 + 2];
                p[rr][0] = a.x; p[rr][1] = a.y; p[rr][2] = bq.x; p[rr][3] = bq.y;
            }
#pragma unroll
            for (int co = 0; co < 4; co++) {
                float4 wa = *(const float4*)&ws[c][co][0];
                float4 wb = *(const float4*)&ws[c][co][4];
                float w8  = ws[c][co][8];
                float w[9] = {wa.x, wa.y, wa.z, wa.w, wb.x, wb.y, wb.z, wb.w, w8};
#pragma unroll
                for (int i = 0; i < 3; i++) {
#pragma unroll
                    for (int j = 0; j < 3; j++) {
                        float wv = w[i * 3 + j];
#pragma unroll
                        for (int r = 0; r < RY; r++) {
                            acc[co][r][0] = fmaf(p[r + i][j],     wv, acc[co][r][0]);
                            acc[co][r][1] = fmaf(p[r + i][j + 1], wv, acc[co][r][1]);
                        }
                    }
                }
            }
        }
    }

    int oy = oy0 + ty * RY;
    int ox = ox0 + tx * 2;
    if (mode == 0) {
#pragma unroll
        for (int co = 0; co < 4; co++) {
            float bz = bias[co0 + co];
            float* op = out + (((size_t)b * Cout + co0 + co) * H + oy) * W + ox;
#pragma unroll
            for (int r = 0; r < RY; r++) {
                float2 f;
                f.x = sigf(acc[co][r][0] + bz);
                f.y = sigf(acc[co][r][1] + bz);
                *(float2*)(op + r * W) = f;
            }
        }
    } else {
#pragma unroll
        for (int co = 0; co < 4; co++) {
            int cc = co0 + co;
            float bz = bias[cc];
            const float* zp = gatesIn + (((size_t)b * 2 * Ch + Ch + cc) * H + oy) * W + ox;
            const float* hp2 = hprev ? hprev + (((size_t)b * Ch + cc) * H + oy) * W + ox
                                     : nullptr;
            float* op = out + (((size_t)b * Ch + cc) * H + oy) * W + ox;
#pragma unroll
            for (int r = 0; r < RY; r++) {
                float2 z = *(const float2*)(zp + r * W);
                float h0 = 0.f, h1 = 0.f;
                if (hp2) {
                    float2 h = *(const float2*)(hp2 + r * W);
                    h0 = h.x; h1 = h.y;
                }
                float2 f;
                f.x = z.x * h0 + (1.f - z.x) * ftanh(acc[co][r][0] + bz);
                f.y = z.y * h1 + (1.f - z.y) * ftanh(acc[co][r][1] + bz);
                *(float2*)(op + r * W) = f;
            }
        }
    }
}

// ---------------------------------------------------------------------------
// Stride-2 3x3 conv (pad 1) + leaky relu(0.2), over all N = T*B samples.
// ---------------------------------------------------------------------------
#define CSTEP2 4
__global__ void conv_s2_lrelu(const float* __restrict__ in, const float* __restrict__ Wt,
                              const float* __restrict__ bias, float* __restrict__ out,
                              int Cin, int Cout, int Hin, int Win, int sOuter, int sInner)
{
    int coutBlocks = Cout >> 3;
    int n  = blockIdx.x / coutBlocks;
    int cb = blockIdx.x % coutBlocks;
    int co0 = cb * 8;
    int t = n / 8, b = n % 8;
    const float* inN = in + (size_t)t * sOuter + (size_t)b * sInner;
    int Hout = Hin >> 1, Wout = Win >> 1;
    int oy0 = blockIdx.y * 16, ox0 = blockIdx.z * 16;
    int tx = threadIdx.x, ty = threadIdx.y;
    int tid = ty * 16 + tx;

    __shared__ float tile[CSTEP2][33][35];
    __shared__ float ws[CSTEP2][8][9];

    float acc0[8], acc1[8];
#pragma unroll
    for (int i = 0; i < 8; i++) { acc0[i] = 0.f; acc1[i] = 0.f; }

    for (int ci0 = 0; ci0 < Cin; ci0 += CSTEP2) {
        __syncthreads();
        for (int i = tid; i < CSTEP2 * 1089; i += 128) {
            int c = i / 1089, p = i % 1089;
            int ly = p / 33, lx = p % 33;
            int gy = 2 * oy0 - 1 + ly, gx = 2 * ox0 - 1 + lx;
            float v = 0.f;
            int ci = ci0 + c;
            if (ci < Cin && gy >= 0 && gy < Hin && gx >= 0 && gx < Win)
                v = inN[((size_t)ci * Hin + gy) * Win + gx];
            tile[c][ly][lx] = v;
        }
        for (int i = tid; i < CSTEP2 * 72; i += 128) {
            int c = i / 72, r = i % 72;
            int co = r / 9, k = r % 9;
            float wv = 0.f;
            if (ci0 + c < Cin)
                wv = Wt[((size_t)(co0 + co) * Cin + (ci0 + c)) * 9 + k];
            ws[c][co][k] = wv;
        }
        __syncthreads();

#pragma unroll
        for (int c = 0; c < CSTEP2; c++) {
            float a[5][3];
#pragma unroll
            for (int i = 0; i < 5; i++)
#pragma unroll
                for (int j = 0; j < 3; j++)
                    a[i][j] = tile[c][4 * ty + i][2 * tx + j];
#pragma unroll
            for (int co = 0; co < 8; co++) {
                float w0 = ws[c][co][0], w1 = ws[c][co][1], w2 = ws[c][co][2];
                float w3 = ws[c][co][3], w4 = ws[c][co][4], w5 = ws[c][co][5];
                float w6 = ws[c][co][6], w7 = ws[c][co][7], w8 = ws[c][co][8];
                acc0[co] += a[0][0]*w0 + a[0][1]*w1 + a[0][2]*w2
                          + a[1][0]*w3 + a[1][1]*w4 + a[1][2]*w5
                          + a[2][0]*w6 + a[2][1]*w7 + a[2][2]*w8;
                acc1[co] += a[2][0]*w0 + a[2][1]*w1 + a[2][2]*w2
                          + a[3][0]*w3 + a[3][1]*w4 + a[3][2]*w5
                          + a[4][0]*w6 + a[4][1]*w7 + a[4][2]*w8;
            }
        }
    }

    int oy = oy0 + 2 * ty, ox = ox0 + tx;
#pragma unroll
    for (int co = 0; co < 8; co++) {
        float bz = bias[co0 + co];
        float v0 = acc0[co] + bz, v1 = acc1[co] + bz;
        v0 = v0 > 0.f ? v0 : 0.2f * v0;
        v1 = v1 > 0.f ? v1 : 0.2f * v1;
        size_t o = (((size_t)n * Cout + co0 + co) * Hout + oy) * Wout + ox;
        out[o]        = v0;
        out[o + Wout] = v1;
    }
}

extern "C" void kernel_launch(void* const* d_in, const int* in_sizes, int n_in,
                              void* d_out, int out_size)
{
    const float* x   = (const float*)d_in[0];
    const float* W1  = (const float*)d_in[1];
    const float* b1  = (const float*)d_in[2];
    const float* Wg1 = (const float*)d_in[3];
    const float* bg1 = (const float*)d_in[4];
    const float* Wc1 = (const float*)d_in[5];
    const float* bc1 = (const float*)d_in[6];
    const float* W2  = (const float*)d_in[7];
    const float* b2  = (const float*)d_in[8];
    const float* Wg2 = (const float*)d_in[9];
    const float* bg2 = (const float*)d_in[10];
    const float* Wc2 = (const float*)d_in[11];
    const float* bc2 = (const float*)d_in[12];
    const float* W3  = (const float*)d_in[13];
    const float* b3  = (const float*)d_in[14];
    const float* Wg3 = (const float*)d_in[15];
    const float* bg3 = (const float*)d_in[16];
    const float* Wc3 = (const float*)d_in[17];
    const float* bc3 = (const float*)d_in[18];

    float* base = nullptr;
    cudaGetSymbolAddress((void**)&base, g_scratch);

    float* feat1 = base;                 // 10*8*16*64*64  = 5242880
    float* outs1 = base + 5242880;       // 10*8*64*64*64  = 20971520
    float* feat2 = base + 26214400;      // 10*8*64*32*32  = 5242880
    float* outs2 = base + 31457280;      // 10*8*96*32*32  = 7864320
    float* feat3 = base + 39321600;      // 10*8*96*16*16  = 1966080
    float* outs3 = base + 41287680;      // 10*8*96*16*16  = 1966080
    float* gates = base + 43253760;      // max 8*128*64*64 = 4194304

    dim3 blkc(16, 8);
    dim3 blkBig(16, 8);   // RY=4, tile 32x32
    dim3 blkSm(8, 16);    // RY=1, tile 16x16

    // ---------------- Stage 1 (H=W=64, Cx=16, Ch=64) ----------------
    conv_s2_lrelu<<<dim3(80 * 2, 4, 4), blkc>>>(x, W1, b1, feat1,
                                                1, 16, 128, 128, 16384, 163840);
    for (int t = 0; t < 10; t++) {
        const float* xt = feat1 + (size_t)t * 8 * 16 * 64 * 64;
        const float* hp = t ? outs1 + (size_t)(t - 1) * 8 * 64 * 64 * 64 : nullptr;
        float* hn = outs1 + (size_t)t * 8 * 64 * 64 * 64;
        gru_conv3<4><<<dim3(8 * 32, 2, 2), blkBig>>>(xt, hp, Wg1, bg1, gates, gates,
                                                     16, 64, 128, 64, 64, 0);
        gru_conv3<4><<<dim3(8 * 16, 2, 2), blkBig>>>(xt, hp, Wc1, bc1, gates, hn,
                                                     16, 64, 64, 64, 64, 1);
    }

    // ---------------- Stage 2 (H=W=32, Cx=64, Ch=96) ----------------
    conv_s2_lrelu<<<dim3(80 * 8, 2, 2), blkc>>>(outs1, W2, b2, feat2,
                                                64, 64, 64, 64, 8 * 64 * 4096, 64 * 4096);
    for (int t = 0; t < 10; t++) {
        const float* xt = feat2 + (size_t)t * 8 * 64 * 32 * 32;
        const float* hp = t ? outs2 + (size_t)(t - 1) * 8 * 96 * 32 * 32 : nullptr;
        float* hn = outs2 + (size_t)t * 8 * 96 * 32 * 32;
        gru_conv3<4><<<dim3(8 * 48, 1, 1), blkBig>>>(xt, hp, Wg2, bg2, gates, gates,
                                                     64, 96, 192, 32, 32, 0);
        gru_conv3<4><<<dim3(8 * 24, 1, 1), blkBig>>>(xt, hp, Wc2, bc2, gates, hn,
                                                     64, 96, 96, 32, 32, 1);
    }

    // ---------------- Stage 3 (H=W=16, Cx=96, Ch=96) ----------------
    conv_s2_lrelu<<<dim3(80 * 12, 1, 1), blkc>>>(outs2, W3, b3, feat3,
                                                 96, 96, 32, 32, 8 * 96 * 1024, 96 * 1024);
    for (int t = 0; t < 10; t++) {
        const float* xt = feat3 + (size_t)t * 8 * 96 * 16 * 16;
        const float* hp = t ? outs3 + (size_t)(t - 1) * 8 * 96 * 16 * 16 : nullptr;
        float* hn = outs3 + (size_t)t * 8 * 96 * 16 * 16;
        gru_conv3<1><<<dim3(8 * 48, 1, 1), blkSm>>>(xt, hp, Wg3, bg3, gates, gates,
                                                    96, 96, 192, 16, 16, 0);
        gru_conv3<1><<<dim3(8 * 24, 1, 1), blkSm>>>(xt, hp, Wc3, bc3, gates, hn,
                                                    96, 96, 96, 16, 16, 1);
    }

    // ---------------- Assemble output: (h1, h2, h3) flattened ----------------
    float* out = (float*)d_out;
    cudaMemcpyAsync(out,
                    outs1 + 9UL * 8 * 64 * 4096,
                    (size_t)8 * 64 * 4096 * sizeof(float),
                    cudaMemcpyDeviceToDevice, 0);
    cudaMemcpyAsync(out + 2097152,
                    outs2 + 9UL * 8 * 96 * 1024,
                    (size_t)8 * 96 * 1024 * sizeof(float),
                    cudaMemcpyDeviceToDevice, 0);
    cudaMemcpyAsync(out + 2097152 + 786432,
                    outs3 + 9UL * 8 * 96 * 256,
                    (size_t)8 * 96 * 256 * sizeof(float),
                    cudaMemcpyDeviceToDevice, 0);
}

// round 6
// speedup vs baseline: 1.7109x; 1.7109x over previous
#include <cuda_runtime.h>
#include <math.h>

#define TS 16
#define CSTEP 8
#define CSTEP2 4

// Scratch: feat1, outs1, feat2, outs2, feat3, outs3, gates (all fp32)
__device__ float g_scratch[47448064];

__device__ __forceinline__ float sigf(float x) { return 1.f / (1.f + __expf(-x)); }

// ---------------------------------------------------------------------------
// Stride-1 3x3 conv (pad 1) for GRU gates (mode 0) and candidate+update (mode 1).
// Input channels: [0,Cx) from xt, [Cx,Cx+Ch) from hprev (mode1: multiplied by r).
// block (16,8): each thread -> 2 output rows x 1 col x 8 output channels.
// grid: (B * Cout/8, H/16, W/16)
// ---------------------------------------------------------------------------
__global__ __launch_bounds__(128)
void gru_conv(const float* __restrict__ xt, const float* __restrict__ hprev,
              const float* __restrict__ Wt, const float* __restrict__ bias,
              const float* __restrict__ gatesIn, float* __restrict__ out,
              int Cx, int Ch, int Cout, int H, int W, int mode)
{
    int coutBlocks = Cout >> 3;
    int b   = blockIdx.x / coutBlocks;
    int cb  = blockIdx.x % coutBlocks;
    int co0 = cb * 8;
    int oy0 = blockIdx.y * TS;
    int ox0 = blockIdx.z * TS;
    int tx = threadIdx.x, ty = threadIdx.y;
    int tid = ty * 16 + tx;

    __shared__ float tile[CSTEP][18][19];
    __shared__ __align__(16) float ws[CSTEP][8][12];

    int CinTot = Cx + Ch;
    int CinEff = hprev ? CinTot : Cx;   // h0 == 0 -> skip h channels at t=0

    float acc0[8], acc1[8];
#pragma unroll
    for (int i = 0; i < 8; i++) { acc0[i] = 0.f; acc1[i] = 0.f; }

    for (int ci0 = 0; ci0 < CinEff; ci0 += CSTEP) {
        __syncthreads();
        // load input tile (18x18 per channel, zero-padded borders)
        for (int i = tid; i < CSTEP * 324; i += 128) {
            int c = i / 324, p = i % 324;
            int ly = p / 18, lx = p % 18;
            int gy = oy0 - 1 + ly, gx = ox0 - 1 + lx;
            float v = 0.f;
            if (gy >= 0 && gy < H && gx >= 0 && gx < W) {
                int ci = ci0 + c;
                if (ci < Cx) {
                    v = xt[(((size_t)b * Cx + ci) * H + gy) * W + gx];
                } else {
                    int ch = ci - Cx;
                    v = hprev[(((size_t)b * Ch + ch) * H + gy) * W + gx];
                    if (mode) v *= gatesIn[(((size_t)b * 2 * Ch + ch) * H + gy) * W + gx]; // r*h
                }
            }
            tile[c][ly][lx] = v;
        }
        // load weights for this (cout block, cin chunk): 8c x 8co x 9
        for (int i = tid; i < CSTEP * 72; i += 128) {
            int c = i / 72, r = i % 72;
            int co = r / 9, k = r % 9;
            ws[c][co][k] = Wt[((size_t)(co0 + co) * CinTot + (ci0 + c)) * 9 + k];
        }
        __syncthreads();

#pragma unroll
        for (int c = 0; c < CSTEP; c++) {
            float a[4][3];
#pragma unroll
            for (int i = 0; i < 4; i++)
#pragma unroll
                for (int j = 0; j < 3; j++)
                    a[i][j] = tile[c][2 * ty + i][tx + j];
#pragma unroll
            for (int co = 0; co < 8; co++) {
                float4 wa = *(const float4*)&ws[c][co][0];
                float4 wb = *(const float4*)&ws[c][co][4];
                float w8  = ws[c][co][8];
                acc0[co] += a[0][0]*wa.x + a[0][1]*wa.y + a[0][2]*wa.z
                          + a[1][0]*wa.w + a[1][1]*wb.x + a[1][2]*wb.y
                          + a[2][0]*wb.z + a[2][1]*wb.w + a[2][2]*w8;
                acc1[co] += a[1][0]*wa.x + a[1][1]*wa.y + a[1][2]*wa.z
                          + a[2][0]*wa.w + a[2][1]*wb.x + a[2][2]*wb.y
                          + a[3][0]*wb.z + a[3][1]*wb.w + a[3][2]*w8;
            }
        }
    }

    int oy = oy0 + 2 * ty, ox = ox0 + tx;
    if (mode == 0) {
#pragma unroll
        for (int co = 0; co < 8; co++) {
            float bz = bias[co0 + co];
            size_t o = (((size_t)b * Cout + co0 + co) * H + oy) * W + ox;
            out[o]     = sigf(acc0[co] + bz);
            out[o + W] = sigf(acc1[co] + bz);
        }
    } else {
#pragma unroll
        for (int co = 0; co < 8; co++) {
            float bz = bias[co0 + co];
            int cc = co0 + co;
            size_t zo = (((size_t)b * 2 * Ch + Ch + cc) * H + oy) * W + ox;
            float z0 = gatesIn[zo], z1 = gatesIn[zo + W];
            float h0v = 0.f, h1v = 0.f;
            if (hprev) {
                size_t ho = (((size_t)b * Ch + cc) * H + oy) * W + ox;
                h0v = hprev[ho]; h1v = hprev[ho + W];
            }
            size_t o = (((size_t)b * Ch + cc) * H + oy) * W + ox;
            out[o]     = z0 * h0v + (1.f - z0) * tanhf(acc0[co] + bz);
            out[o + W] = z1 * h1v + (1.f - z1) * tanhf(acc1[co] + bz);
        }
    }
}

// ---------------------------------------------------------------------------
// Stride-2 3x3 conv (pad 1) + leaky relu(0.2), over all N = T*B samples.
// block (16,8): each thread -> 2 output rows x 1 col x 8 output channels.
// grid: (N * Cout/8, Hout/16, Wout/16)
// ---------------------------------------------------------------------------
__global__ void conv_s2_lrelu(const float* __restrict__ in, const float* __restrict__ Wt,
                              const float* __restrict__ bias, float* __restrict__ out,
                              int Cin, int Cout, int Hin, int Win, int sOuter, int sInner)
{
    int coutBlocks = Cout >> 3;
    int n  = blockIdx.x / coutBlocks;
    int cb = blockIdx.x % coutBlocks;
    int co0 = cb * 8;
    int t = n / 8, b = n % 8;
    const float* inN = in + (size_t)t * sOuter + (size_t)b * sInner;
    int Hout = Hin >> 1, Wout = Win >> 1;
    int oy0 = blockIdx.y * TS, ox0 = blockIdx.z * TS;
    int tx = threadIdx.x, ty = threadIdx.y;
    int tid = ty * 16 + tx;

    __shared__ float tile[CSTEP2][33][35];
    __shared__ float ws[CSTEP2][8][9];

    float acc0[8], acc1[8];
#pragma unroll
    for (int i = 0; i < 8; i++) { acc0[i] = 0.f; acc1[i] = 0.f; }

    for (int ci0 = 0; ci0 < Cin; ci0 += CSTEP2) {
        __syncthreads();
        for (int i = tid; i < CSTEP2 * 1089; i += 128) {
            int c = i / 1089, p = i % 1089;
            int ly = p / 33, lx = p % 33;
            int gy = 2 * oy0 - 1 + ly, gx = 2 * ox0 - 1 + lx;
            float v = 0.f;
            int ci = ci0 + c;
            if (ci < Cin && gy >= 0 && gy < Hin && gx >= 0 && gx < Win)
                v = inN[((size_t)ci * Hin + gy) * Win + gx];
            tile[c][ly][lx] = v;
        }
        for (int i = tid; i < CSTEP2 * 72; i += 128) {
            int c = i / 72, r = i % 72;
            int co = r / 9, k = r % 9;
            float wv = 0.f;
            if (ci0 + c < Cin)
                wv = Wt[((size_t)(co0 + co) * Cin + (ci0 + c)) * 9 + k];
            ws[c][co][k] = wv;
        }
        __syncthreads();

#pragma unroll
        for (int c = 0; c < CSTEP2; c++) {
            float a[5][3];
#pragma unroll
            for (int i = 0; i < 5; i++)
#pragma unroll
                for (int j = 0; j < 3; j++)
                    a[i][j] = tile[c][4 * ty + i][2 * tx + j];
#pragma unroll
            for (int co = 0; co < 8; co++) {
                float w0 = ws[c][co][0], w1 = ws[c][co][1], w2 = ws[c][co][2];
                float w3 = ws[c][co][3], w4 = ws[c][co][4], w5 = ws[c][co][5];
                float w6 = ws[c][co][6], w7 = ws[c][co][7], w8 = ws[c][co][8];
                acc0[co] += a[0][0]*w0 + a[0][1]*w1 + a[0][2]*w2
                          + a[1][0]*w3 + a[1][1]*w4 + a[1][2]*w5
                          + a[2][0]*w6 + a[2][1]*w7 + a[2][2]*w8;
                acc1[co] += a[2][0]*w0 + a[2][1]*w1 + a[2][2]*w2
                          + a[3][0]*w3 + a[3][1]*w4 + a[3][2]*w5
                          + a[4][0]*w6 + a[4][1]*w7 + a[4][2]*w8;
            }
        }
    }

    int oy = oy0 + 2 * ty, ox = ox0 + tx;
#pragma unroll
    for (int co = 0; co < 8; co++) {
        float bz = bias[co0 + co];
        float v0 = acc0[co] + bz, v1 = acc1[co] + bz;
        v0 = v0 > 0.f ? v0 : 0.2f * v0;
        v1 = v1 > 0.f ? v1 : 0.2f * v1;
        size_t o = (((size_t)n * Cout + co0 + co) * Hout + oy) * Wout + ox;
        out[o]        = v0;
        out[o + Wout] = v1;
    }
}

extern "C" void kernel_launch(void* const* d_in, const int* in_sizes, int n_in,
                              void* d_out, int out_size)
{
    const float* x   = (const float*)d_in[0];
    const float* W1  = (const float*)d_in[1];
    const float* b1  = (const float*)d_in[2];
    const float* Wg1 = (const float*)d_in[3];
    const float* bg1 = (const float*)d_in[4];
    const float* Wc1 = (const float*)d_in[5];
    const float* bc1 = (const float*)d_in[6];
    const float* W2  = (const float*)d_in[7];
    const float* b2  = (const float*)d_in[8];
    const float* Wg2 = (const float*)d_in[9];
    const float* bg2 = (const float*)d_in[10];
    const float* Wc2 = (const float*)d_in[11];
    const float* bc2 = (const float*)d_in[12];
    const float* W3  = (const float*)d_in[13];
    const float* b3  = (const float*)d_in[14];
    const float* Wg3 = (const float*)d_in[15];
    const float* bg3 = (const float*)d_in[16];
    const float* Wc3 = (const float*)d_in[17];
    const float* bc3 = (const float*)d_in[18];

    float* base = nullptr;
    cudaGetSymbolAddress((void**)&base, g_scratch);

    float* feat1 = base;                 // 10*8*16*64*64  = 5242880
    float* outs1 = base + 5242880;       // 10*8*64*64*64  = 20971520
    float* feat2 = base + 26214400;      // 10*8*64*32*32  = 5242880
    float* outs2 = base + 31457280;      // 10*8*96*32*32  = 7864320
    float* feat3 = base + 39321600;      // 10*8*96*16*16  = 1966080
    float* outs3 = base + 41287680;      // 10*8*96*16*16  = 1966080
    float* gates = base + 43253760;      // max 8*128*64*64 = 4194304

    dim3 blk(16, 8);

    // ---------------- Stage 1 ----------------
    conv_s2_lrelu<<<dim3(80 * 2, 4, 4), blk>>>(x, W1, b1, feat1,
                                               1, 16, 128, 128, 16384, 163840);
    for (int t = 0; t < 10; t++) {
        const float* xt = feat1 + (size_t)t * 8 * 16 * 64 * 64;
        const float* hp = t ? outs1 + (size_t)(t - 1) * 8 * 64 * 64 * 64 : nullptr;
        float* hn = outs1 + (size_t)t * 8 * 64 * 64 * 64;
        gru_conv<<<dim3(8 * 16, 4, 4), blk>>>(xt, hp, Wg1, bg1, gates, gates,
                                              16, 64, 128, 64, 64, 0);
        gru_conv<<<dim3(8 * 8, 4, 4), blk>>>(xt, hp, Wc1, bc1, gates, hn,
                                             16, 64, 64, 64, 64, 1);
    }

    // ---------------- Stage 2 ----------------
    conv_s2_lrelu<<<dim3(80 * 8, 2, 2), blk>>>(outs1, W2, b2, feat2,
                                               64, 64, 64, 64, 8 * 64 * 4096, 64 * 4096);
    for (int t = 0; t < 10; t++) {
        const float* xt = feat2 + (size_t)t * 8 * 64 * 32 * 32;
        const float* hp = t ? outs2 + (size_t)(t - 1) * 8 * 96 * 32 * 32 : nullptr;
        float* hn = outs2 + (size_t)t * 8 * 96 * 32 * 32;
        gru_conv<<<dim3(8 * 24, 2, 2), blk>>>(xt, hp, Wg2, bg2, gates, gates,
                                              64, 96, 192, 32, 32, 0);
        gru_conv<<<dim3(8 * 12, 2, 2), blk>>>(xt, hp, Wc2, bc2, gates, hn,
                                              64, 96, 96, 32, 32, 1);
    }

    // ---------------- Stage 3 ----------------
    conv_s2_lrelu<<<dim3(80 * 12, 1, 1), blk>>>(outs2, W3, b3, feat3,
                                                96, 96, 32, 32, 8 * 96 * 1024, 96 * 1024);
    for (int t = 0; t < 10; t++) {
        const float* xt = feat3 + (size_t)t * 8 * 96 * 16 * 16;
        const float* hp = t ? outs3 + (size_t)(t - 1) * 8 * 96 * 16 * 16 : nullptr;
        float* hn = outs3 + (size_t)t * 8 * 96 * 16 * 16;
        gru_conv<<<dim3(8 * 24, 1, 1), blk>>>(xt, hp, Wg3, bg3, gates, gates,
                                              96, 96, 192, 16, 16, 0);
        gru_conv<<<dim3(8 * 12, 1, 1), blk>>>(xt, hp, Wc3, bc3, gates, hn,
                                              96, 96, 96, 16, 16, 1);
    }

    // ---------------- Assemble output: (h1, h2, h3) flattened ----------------
    float* out = (float*)d_out;
    cudaMemcpyAsync(out,
                    outs1 + 9UL * 8 * 64 * 4096,
                    (size_t)8 * 64 * 4096 * sizeof(float),
                    cudaMemcpyDeviceToDevice, 0);
    cudaMemcpyAsync(out + 2097152,
                    outs2 + 9UL * 8 * 96 * 1024,
                    (size_t)8 * 96 * 1024 * sizeof(float),
                    cudaMemcpyDeviceToDevice, 0);
    cudaMemcpyAsync(out + 2097152 + 786432,
                    outs3 + 9UL * 8 * 96 * 256,
                    (size_t)8 * 96 * 256 * sizeof(float),
                    cudaMemcpyDeviceToDevice, 0);
}

// round 8
// speedup vs baseline: 2.1990x; 1.2853x over previous
#include <cuda_runtime.h>
#include <math.h>

#define TS 16
#define CSTEP 8
#define CSTEP2 4

// Scratch (fp32): feat/outs/gates + hoisted x-part conv results
__device__ float g_scratch[139853824];

__device__ __forceinline__ float sigf(float x) { return 1.f / (1.f + __expf(-x)); }
__device__ __forceinline__ float ftanh(float x) {
    float e = __expf(2.f * x);
    return 1.f - 2.f / (e + 1.f);
}

// ---------------------------------------------------------------------------
// Batched stride-1 3x3 conv (pad 1), raw output + bias. N samples contiguous.
// in: (N, Cin, H, W), weights OIHW with row stride CinTot (x-part slice),
// out: (N, Cout, H, W).   block (16,8), 8 couts/block.
// grid: (N * Cout/8, H/16, W/16)
// ---------------------------------------------------------------------------
__global__ __launch_bounds__(128)
void conv_pre(const float* __restrict__ in, const float* __restrict__ Wt,
              const float* __restrict__ bias, float* __restrict__ out,
              int Cin, int CinTot, int Cout, int H, int W)
{
    int coutBlocks = Cout >> 3;
    int n   = blockIdx.x / coutBlocks;
    int co0 = (blockIdx.x % coutBlocks) * 8;
    int oy0 = blockIdx.y * TS;
    int ox0 = blockIdx.z * TS;
    int tx = threadIdx.x, ty = threadIdx.y;
    int tid = ty * 16 + tx;

    __shared__ float tile[CSTEP][18][19];
    __shared__ __align__(16) float ws[CSTEP][8][12];

    int HW = H * W;
    const float* inN = in + (size_t)n * Cin * HW;

    float acc0[8], acc1[8];
#pragma unroll
    for (int i = 0; i < 8; i++) { acc0[i] = 0.f; acc1[i] = 0.f; }

    for (int ci0 = 0; ci0 < Cin; ci0 += CSTEP) {
        __syncthreads();
        for (int i = tid; i < CSTEP * 324; i += 128) {
            int c = i / 324, p = i % 324;
            int ly = p / 18, lx = p % 18;
            int gy = oy0 - 1 + ly, gx = ox0 - 1 + lx;
            float v = 0.f;
            if (gy >= 0 && gy < H && gx >= 0 && gx < W)
                v = inN[(size_t)(ci0 + c) * HW + gy * W + gx];
            tile[c][ly][lx] = v;
        }
        for (int i = tid; i < CSTEP * 72; i += 128) {
            int c = i / 72, r = i % 72;
            int co = r / 9, k = r % 9;
            ws[c][co][k] = Wt[((size_t)(co0 + co) * CinTot + (ci0 + c)) * 9 + k];
        }
        __syncthreads();

#pragma unroll
        for (int c = 0; c < CSTEP; c++) {
            float a[4][3];
#pragma unroll
            for (int i = 0; i < 4; i++)
#pragma unroll
                for (int j = 0; j < 3; j++)
                    a[i][j] = tile[c][2 * ty + i][tx + j];
#pragma unroll
            for (int co = 0; co < 8; co++) {
                float4 wa = *(const float4*)&ws[c][co][0];
                float4 wb = *(const float4*)&ws[c][co][4];
                float w8  = ws[c][co][8];
                acc0[co] += a[0][0]*wa.x + a[0][1]*wa.y + a[0][2]*wa.z
                          + a[1][0]*wa.w + a[1][1]*wb.x + a[1][2]*wb.y
                          + a[2][0]*wb.z + a[2][1]*wb.w + a[2][2]*w8;
                acc1[co] += a[1][0]*wa.x + a[1][1]*wa.y + a[1][2]*wa.z
                          + a[2][0]*wa.w + a[2][1]*wb.x + a[2][2]*wb.y
                          + a[3][0]*wb.z + a[3][1]*wb.w + a[3][2]*w8;
            }
        }
    }

    int oy = oy0 + 2 * ty, ox = ox0 + tx;
#pragma unroll
    for (int co = 0; co < 8; co++) {
        float bz = bias[co0 + co];
        size_t o = ((size_t)n * Cout + co0 + co) * HW + (size_t)oy * W + ox;
        out[o]     = acc0[co] + bz;
        out[o + W] = acc1[co] + bz;
    }
}

// ---------------------------------------------------------------------------
// Recurrent h-part conv (t >= 1). Conv over Ch channels of hprev (mode 1:
// multiplied by r from gatesIn), accumulator seeded by precomputed pre
// (= bias + x-part).  pre layout (B, Cout, H, W) for this timestep.
// mode 0: gates -> sigmoid.  mode 1: cand -> GRU update.
// grid: (B * Cout/8, H/16, W/16)
// ---------------------------------------------------------------------------
__global__ __launch_bounds__(128)
void gru_conv_h(const float* __restrict__ hprev, const float* __restrict__ Wt,
                const float* __restrict__ pre, const float* __restrict__ gatesIn,
                float* __restrict__ out,
                int Cx, int CinTot, int Ch, int Cout, int H, int W, int mode)
{
    int coutBlocks = Cout >> 3;
    int b   = blockIdx.x / coutBlocks;
    int co0 = (blockIdx.x % coutBlocks) * 8;
    int oy0 = blockIdx.y * TS;
    int ox0 = blockIdx.z * TS;
    int tx = threadIdx.x, ty = threadIdx.y;
    int tid = ty * 16 + tx;

    __shared__ float tile[CSTEP][18][19];
    __shared__ __align__(16) float ws[CSTEP][8][12];

    int HW = H * W;

    float acc0[8], acc1[8];
#pragma unroll
    for (int i = 0; i < 8; i++) { acc0[i] = 0.f; acc1[i] = 0.f; }

    for (int ci0 = 0; ci0 < Ch; ci0 += CSTEP) {
        __syncthreads();
        for (int i = tid; i < CSTEP * 324; i += 128) {
            int c = i / 324, p = i % 324;
            int ly = p / 18, lx = p % 18;
            int gy = oy0 - 1 + ly, gx = ox0 - 1 + lx;
            float v = 0.f;
            if (gy >= 0 && gy < H && gx >= 0 && gx < W) {
                int ch = ci0 + c;
                v = hprev[(((size_t)b * Ch + ch) * H + gy) * W + gx];
                if (mode) v *= gatesIn[(((size_t)b * 2 * Ch + ch) * H + gy) * W + gx]; // r*h
            }
            tile[c][ly][lx] = v;
        }
        for (int i = tid; i < CSTEP * 72; i += 128) {
            int c = i / 72, r = i % 72;
            int co = r / 9, k = r % 9;
            ws[c][co][k] = Wt[((size_t)(co0 + co) * CinTot + Cx + (ci0 + c)) * 9 + k];
        }
        __syncthreads();

#pragma unroll
        for (int c = 0; c < CSTEP; c++) {
            float a[4][3];
#pragma unroll
            for (int i = 0; i < 4; i++)
#pragma unroll
                for (int j = 0; j < 3; j++)
                    a[i][j] = tile[c][2 * ty + i][tx + j];
#pragma unroll
            for (int co = 0; co < 8; co++) {
                float4 wa = *(const float4*)&ws[c][co][0];
                float4 wb = *(const float4*)&ws[c][co][4];
                float w8  = ws[c][co][8];
                acc0[co] += a[0][0]*wa.x + a[0][1]*wa.y + a[0][2]*wa.z
                          + a[1][0]*wa.w + a[1][1]*wb.x + a[1][2]*wb.y
                          + a[2][0]*wb.z + a[2][1]*wb.w + a[2][2]*w8;
                acc1[co] += a[1][0]*wa.x + a[1][1]*wa.y + a[1][2]*wa.z
                          + a[2][0]*wa.w + a[2][1]*wb.x + a[2][2]*wb.y
                          + a[3][0]*wb.z + a[3][1]*wb.w + a[3][2]*w8;
            }
        }
    }

    int oy = oy0 + 2 * ty, ox = ox0 + tx;
    if (mode == 0) {
#pragma unroll
        for (int co = 0; co < 8; co++) {
            size_t po = ((size_t)b * Cout + co0 + co) * HW + (size_t)oy * W + ox;
            float p0 = pre[po], p1 = pre[po + W];
            size_t o = (((size_t)b * Cout + co0 + co) * H + oy) * W + ox;
            out[o]     = sigf(acc0[co] + p0);
            out[o + W] = sigf(acc1[co] + p1);
        }
    } else {
#pragma unroll
        for (int co = 0; co < 8; co++) {
            int cc = co0 + co;
            size_t po = ((size_t)b * Cout + cc) * HW + (size_t)oy * W + ox;
            float p0 = pre[po], p1 = pre[po + W];
            size_t zo = (((size_t)b * 2 * Ch + Ch + cc) * H + oy) * W + ox;
            float z0 = gatesIn[zo], z1 = gatesIn[zo + W];
            size_t ho = (((size_t)b * Ch + cc) * H + oy) * W + ox;
            float h0v = hprev[ho], h1v = hprev[ho + W];
            out[ho]     = z0 * h0v + (1.f - z0) * ftanh(acc0[co] + p0);
            out[ho + W] = z1 * h1v + (1.f - z1) * ftanh(acc1[co] + p1);
        }
    }
}

// ---------------------------------------------------------------------------
// t = 0 step (h == 0): hn = (1 - sigmoid(z_pre)) * tanh(c_pre), elementwise.
// gz: (B, 2Ch, HW) pre for gates; gc: (B, Ch, HW) pre for cand.
// ---------------------------------------------------------------------------
__global__ void gru_t0(const float* __restrict__ gz, const float* __restrict__ gc,
                       float* __restrict__ hn, int Ch, int HW, int total)
{
    int i = blockIdx.x * 256 + threadIdx.x;
    if (i >= total) return;
    int b = i / (Ch * HW);
    float z = sigf(gz[(size_t)i + (size_t)(b + 1) * Ch * HW]);
    hn[i] = (1.f - z) * ftanh(gc[i]);
}

// ---------------------------------------------------------------------------
// Stride-2 3x3 conv (pad 1) + leaky relu(0.2), over all N = T*B samples.
// ---------------------------------------------------------------------------
__global__ void conv_s2_lrelu(const float* __restrict__ in, const float* __restrict__ Wt,
                              const float* __restrict__ bias, float* __restrict__ out,
                              int Cin, int Cout, int Hin, int Win, int sOuter, int sInner)
{
    int coutBlocks = Cout >> 3;
    int n  = blockIdx.x / coutBlocks;
    int cb = blockIdx.x % coutBlocks;
    int co0 = cb * 8;
    int t = n / 8, b = n % 8;
    const float* inN = in + (size_t)t * sOuter + (size_t)b * sInner;
    int Hout = Hin >> 1, Wout = Win >> 1;
    int oy0 = blockIdx.y * TS, ox0 = blockIdx.z * TS;
    int tx = threadIdx.x, ty = threadIdx.y;
    int tid = ty * 16 + tx;

    __shared__ float tile[CSTEP2][33][35];
    __shared__ float ws[CSTEP2][8][9];

    float acc0[8], acc1[8];
#pragma unroll
    for (int i = 0; i < 8; i++) { acc0[i] = 0.f; acc1[i] = 0.f; }

    for (int ci0 = 0; ci0 < Cin; ci0 += CSTEP2) {
        __syncthreads();
        for (int i = tid; i < CSTEP2 * 1089; i += 128) {
            int c = i / 1089, p = i % 1089;
            int ly = p / 33, lx = p % 33;
            int gy = 2 * oy0 - 1 + ly, gx = 2 * ox0 - 1 + lx;
            float v = 0.f;
            int ci = ci0 + c;
            if (ci < Cin && gy >= 0 && gy < Hin && gx >= 0 && gx < Win)
                v = inN[((size_t)ci * Hin + gy) * Win + gx];
            tile[c][ly][lx] = v;
        }
        for (int i = tid; i < CSTEP2 * 72; i += 128) {
            int c = i / 72, r = i % 72;
            int co = r / 9, k = r % 9;
            float wv = 0.f;
            if (ci0 + c < Cin)
                wv = Wt[((size_t)(co0 + co) * Cin + (ci0 + c)) * 9 + k];
            ws[c][co][k] = wv;
        }
        __syncthreads();

#pragma unroll
        for (int c = 0; c < CSTEP2; c++) {
            float a[5][3];
#pragma unroll
            for (int i = 0; i < 5; i++)
#pragma unroll
                for (int j = 0; j < 3; j++)
                    a[i][j] = tile[c][4 * ty + i][2 * tx + j];
#pragma unroll
            for (int co = 0; co < 8; co++) {
                float w0 = ws[c][co][0], w1 = ws[c][co][1], w2 = ws[c][co][2];
                float w3 = ws[c][co][3], w4 = ws[c][co][4], w5 = ws[c][co][5];
                float w6 = ws[c][co][6], w7 = ws[c][co][7], w8 = ws[c][co][8];
                acc0[co] += a[0][0]*w0 + a[0][1]*w1 + a[0][2]*w2
                          + a[1][0]*w3 + a[1][1]*w4 + a[1][2]*w5
                          + a[2][0]*w6 + a[2][1]*w7 + a[2][2]*w8;
                acc1[co] += a[2][0]*w0 + a[2][1]*w1 + a[2][2]*w2
                          + a[3][0]*w3 + a[3][1]*w4 + a[3][2]*w5
                          + a[4][0]*w6 + a[4][1]*w7 + a[4][2]*w8;
            }
        }
    }

    int oy = oy0 + 2 * ty, ox = ox0 + tx;
#pragma unroll
    for (int co = 0; co < 8; co++) {
        float bz = bias[co0 + co];
        float v0 = acc0[co] + bz, v1 = acc1[co] + bz;
        v0 = v0 > 0.f ? v0 : 0.2f * v0;
        v1 = v1 > 0.f ? v1 : 0.2f * v1;
        size_t o = (((size_t)n * Cout + co0 + co) * Hout + oy) * Wout + ox;
        out[o]        = v0;
        out[o + Wout] = v1;
    }
}

extern "C" void kernel_launch(void* const* d_in, const int* in_sizes, int n_in,
                              void* d_out, int out_size)
{
    const float* x   = (const float*)d_in[0];
    const float* W1  = (const float*)d_in[1];
    const float* b1  = (const float*)d_in[2];
    const float* Wg1 = (const float*)d_in[3];
    const float* bg1 = (const float*)d_in[4];
    const float* Wc1 = (const float*)d_in[5];
    const float* bc1 = (const float*)d_in[6];
    const float* W2  = (const float*)d_in[7];
    const float* b2  = (const float*)d_in[8];
    const float* Wg2 = (const float*)d_in[9];
    const float* bg2 = (const float*)d_in[10];
    const float* Wc2 = (const float*)d_in[11];
    const float* bc2 = (const float*)d_in[12];
    const float* W3  = (const float*)d_in[13];
    const float* b3  = (const float*)d_in[14];
    const float* Wg3 = (const float*)d_in[15];
    const float* bg3 = (const float*)d_in[16];
    const float* Wc3 = (const float*)d_in[17];
    const float* bc3 = (const float*)d_in[18];

    float* base = nullptr;
    cudaGetSymbolAddress((void**)&base, g_scratch);

    float* feat1 = base;                   // 10*8*16*64*64  = 5,242,880
    float* outs1 = base + 5242880;         // 10*8*64*64*64  = 20,971,520
    float* feat2 = base + 26214400;        // 10*8*64*32*32  = 5,242,880
    float* outs2 = base + 31457280;        // 10*8*96*32*32  = 7,864,320
    float* feat3 = base + 39321600;        // 10*8*96*16*16  = 1,966,080
    float* outs3 = base + 41287680;        // 10*8*96*16*16  = 1,966,080
    float* gates = base + 43253760;        // 8*192*64*64 max -> 4,194,304
    float* gxg1  = base + 47448064;        // 80*128*4096 = 41,943,040
    float* gxc1  = base + 89391104;        // 80*64*4096  = 20,971,520
    float* gxg2  = base + 110362624;       // 80*192*1024 = 15,728,640
    float* gxc2  = base + 126091264;       // 80*96*1024  =  7,864,320
    float* gxg3  = base + 133955584;       // 80*192*256  =  3,932,160
    float* gxc3  = base + 137887744;       // 80*96*256   =  1,966,080

    dim3 blk(16, 8);

    // ================= Stage 1 (H=W=64, Cx=16, Ch=64) =================
    conv_s2_lrelu<<<dim3(80 * 2, 4, 4), blk>>>(x, W1, b1, feat1,
                                               1, 16, 128, 128, 16384, 163840);
    conv_pre<<<dim3(80 * 16, 4, 4), blk>>>(feat1, Wg1, bg1, gxg1, 16, 80, 128, 64, 64);
    conv_pre<<<dim3(80 * 8, 4, 4), blk>>>(feat1, Wc1, bc1, gxc1, 16, 80, 64, 64, 64);
    gru_t0<<<(8 * 64 * 4096 + 255) / 256, 256>>>(gxg1, gxc1, outs1, 64, 4096, 8 * 64 * 4096);
    for (int t = 1; t < 10; t++) {
        const float* hp = outs1 + (size_t)(t - 1) * 8 * 64 * 4096;
        float* hn = outs1 + (size_t)t * 8 * 64 * 4096;
        gru_conv_h<<<dim3(8 * 16, 4, 4), blk>>>(hp, Wg1, gxg1 + (size_t)t * 8 * 128 * 4096,
                                                gates, gates, 16, 80, 64, 128, 64, 64, 0);
        gru_conv_h<<<dim3(8 * 8, 4, 4), blk>>>(hp, Wc1, gxc1 + (size_t)t * 8 * 64 * 4096,
                                               gates, hn, 16, 80, 64, 64, 64, 64, 1);
    }

    // ================= Stage 2 (H=W=32, Cx=64, Ch=96) =================
    conv_s2_lrelu<<<dim3(80 * 8, 2, 2), blk>>>(outs1, W2, b2, feat2,
                                               64, 64, 64, 64, 8 * 64 * 4096, 64 * 4096);
    conv_pre<<<dim3(80 * 24, 2, 2), blk>>>(feat2, Wg2, bg2, gxg2, 64, 160, 192, 32, 32);
    conv_pre<<<dim3(80 * 12, 2, 2), blk>>>(feat2, Wc2, bc2, gxc2, 64, 160, 96, 32, 32);
    gru_t0<<<(8 * 96 * 1024 + 255) / 256, 256>>>(gxg2, gxc2, outs2, 96, 1024, 8 * 96 * 1024);
    for (int t = 1; t < 10; t++) {
        const float* hp = outs2 + (size_t)(t - 1) * 8 * 96 * 1024;
        float* hn = outs2 + (size_t)t * 8 * 96 * 1024;
        gru_conv_h<<<dim3(8 * 24, 2, 2), blk>>>(hp, Wg2, gxg2 + (size_t)t * 8 * 192 * 1024,
                                                gates, gates, 64, 160, 96, 192, 32, 32, 0);
        gru_conv_h<<<dim3(8 * 12, 2, 2), blk>>>(hp, Wc2, gxc2 + (size_t)t * 8 * 96 * 1024,
                                                gates, hn, 64, 160, 96, 96, 32, 32, 1);
    }

    // ================= Stage 3 (H=W=16, Cx=96, Ch=96) =================
    conv_s2_lrelu<<<dim3(80 * 12, 1, 1), blk>>>(outs2, W3, b3, feat3,
                                                96, 96, 32, 32, 8 * 96 * 1024, 96 * 1024);
    conv_pre<<<dim3(80 * 24, 1, 1), blk>>>(feat3, Wg3, bg3, gxg3, 96, 192, 192, 16, 16);
    conv_pre<<<dim3(80 * 12, 1, 1), blk>>>(feat3, Wc3, bc3, gxc3, 96, 192, 96, 16, 16);
    gru_t0<<<(8 * 96 * 256 + 255) / 256, 256>>>(gxg3, gxc3, outs3, 96, 256, 8 * 96 * 256);
    for (int t = 1; t < 10; t++) {
        const float* hp = outs3 + (size_t)(t - 1) * 8 * 96 * 256;
        float* hn = outs3 + (size_t)t * 8 * 96 * 256;
        gru_conv_h<<<dim3(8 * 24, 1, 1), blk>>>(hp, Wg3, gxg3 + (size_t)t * 8 * 192 * 256,
                                                gates, gates, 96, 192, 96, 192, 16, 16, 0);
        gru_conv_h<<<dim3(8 * 12, 1, 1), blk>>>(hp, Wc3, gxc3 + (size_t)t * 8 * 96 * 256,
                                                gates, hn, 96, 192, 96, 96, 16, 16, 1);
    }

    // ---------------- Assemble output: (h1, h2, h3) flattened ----------------
    float* out = (float*)d_out;
    cudaMemcpyAsync(out,
                    outs1 + 9UL * 8 * 64 * 4096,
                    (size_t)8 * 64 * 4096 * sizeof(float),
                    cudaMemcpyDeviceToDevice, 0);
    cudaMemcpyAsync(out + 2097152,
                    outs2 + 9UL * 8 * 96 * 1024,
                    (size_t)8 * 96 * 1024 * sizeof(float),
                    cudaMemcpyDeviceToDevice, 0);
    cudaMemcpyAsync(out + 2097152 + 786432,
                    outs3 + 9UL * 8 * 96 * 256,
                    (size_t)8 * 96 * 256 * sizeof(float),
                    cudaMemcpyDeviceToDevice, 0);
}